// round 9
// baseline (speedup 1.0000x reference)
#include <cuda_runtime.h>
#include <cstdint>
#include <cuda_fp16.h>
#include <mma.h>
using namespace nvcuda;

// Problem constants
#define Bb 2
#define Tt 16
#define Hh 32
#define Ww 32
#define Cc 768
#define NHh 12
#define HDd 64
#define NTOK (Bb*Tt*Hh*Ww)      // 32768
#define F3 (3*Cc)               // 2304

// Scratch (no allocations allowed — device globals)
__device__ __half g_yh[NTOK * Cc];      // LN output (half)
__device__ float  g_qkv[NTOK * F3];     // QKV GEMM output (fp32)
__device__ float  g_o[NTOK * Cc];       // attention output (fp32)
__device__ __half g_wqh[F3 * Cc];       // half Wqkv
__device__ __half g_woh[Cc * Cc];       // half Wout

// ---------------------------------------------------------------------------
// float -> half conversion pre-pass (float4 -> 4 halfs)
// ---------------------------------------------------------------------------
__global__ void f2h_kernel(const float* __restrict__ in,
                           __half* __restrict__ out, int n4) {
    int i = blockIdx.x * 256 + threadIdx.x;
    if (i < n4) {
        float4 v = ((const float4*)in)[i];
        ((__half2*)out)[2 * i]     = __floats2half2_rn(v.x, v.y);
        ((__half2*)out)[2 * i + 1] = __floats2half2_rn(v.z, v.w);
    }
}

// ---------------------------------------------------------------------------
// LayerNorm: one block (192 threads) per token; output in fp16
// ---------------------------------------------------------------------------
__global__ void ln_kernel(const float* __restrict__ x,
                          const float* __restrict__ w,
                          const float* __restrict__ b,
                          __half* __restrict__ y) {
    int tok = blockIdx.x;
    int t = threadIdx.x;
    const float4* xr = (const float4*)(x + (size_t)tok * Cc);
    __half2* yr = (__half2*)(y + (size_t)tok * Cc);

    float4 v = xr[t];
    float s  = v.x + v.y + v.z + v.w;
    float ss = v.x*v.x + v.y*v.y + v.z*v.z + v.w*v.w;

    __shared__ float reds[6], redss[6];
    #pragma unroll
    for (int o = 16; o; o >>= 1) {
        s  += __shfl_xor_sync(0xffffffffu, s,  o);
        ss += __shfl_xor_sync(0xffffffffu, ss, o);
    }
    int wid = t >> 5, lid = t & 31;
    if (lid == 0) { reds[wid] = s; redss[wid] = ss; }
    __syncthreads();
    if (t < 32) {
        s  = (lid < 6) ? reds[lid]  : 0.f;
        ss = (lid < 6) ? redss[lid] : 0.f;
        #pragma unroll
        for (int o = 4; o; o >>= 1) {
            s  += __shfl_xor_sync(0xffffffffu, s,  o);
            ss += __shfl_xor_sync(0xffffffffu, ss, o);
        }
        if (lid == 0) { reds[0] = s; redss[0] = ss; }
    }
    __syncthreads();
    float mu  = reds[0] * (1.0f / Cc);
    float var = redss[0] * (1.0f / Cc) - mu * mu;
    float rstd = rsqrtf(var + 1e-5f);

    float4 wv = ((const float4*)w)[t];
    float4 bv = ((const float4*)b)[t];
    float rx = (v.x - mu) * rstd * wv.x + bv.x;
    float ry = (v.y - mu) * rstd * wv.y + bv.y;
    float rz = (v.z - mu) * rstd * wv.z + bv.z;
    float rw = (v.w - mu) * rstd * wv.w + bv.w;
    yr[2 * t]     = __floats2half2_rn(rx, ry);
    yr[2 * t + 1] = __floats2half2_rn(rz, rw);
}

// ---------------------------------------------------------------------------
// FP16 wmma GEMM (fp32 accumulate), 3-stage cp.async, 1 barrier/iter.
// Block 128x128, 4 warps (2m x 2n), warp tile 64x64 (4x4 wmma frags).
// ---------------------------------------------------------------------------
#define BM 128
#define BN 128
#define BKH 32
#define SSTRH 40
#define LDC 132
#define STAGES 3
#define NTHR 128
#define STAGE_H ((BM + BN) * SSTRH)            // 10240 halfs = 20480 B
#define PIPE_BYTES (STAGES * STAGE_H * 2)      // 61440
#define EPI_BYTES (BM * LDC * 4)               // 67584
#define GEMM_SMEM_BYTES (EPI_BYTES > PIPE_BYTES ? EPI_BYTES : PIPE_BYTES)

__device__ __forceinline__ void cp_async16(void* smem_dst, const void* gmem_src) {
    unsigned s = (unsigned)__cvta_generic_to_shared(smem_dst);
    asm volatile("cp.async.cg.shared.global [%0], [%1], 16;\n" :: "r"(s), "l"(gmem_src));
}
#define CP_COMMIT() asm volatile("cp.async.commit_group;\n" ::: "memory")
#define CP_WAIT_N(n) asm volatile("cp.async.wait_group %0;\n" :: "n"(n) : "memory")

template <bool RES>
__global__ void __launch_bounds__(NTHR, 2) gemm_fp16(
        const __half* __restrict__ A,
        const __half* __restrict__ Wt,
        const float* __restrict__ bias,
        const float* __restrict__ res,
        float* __restrict__ Cout,
        int N, int K) {
    extern __shared__ __align__(16) char smem_raw[];
    __half* hs = (__half*)smem_raw;

    int tid = threadIdx.x;
    int m0 = blockIdx.y * BM;
    int n0 = blockIdx.x * BN;

    // Load mapping: thread t owns A row t and B row t (4 x 16B chunks each).
    const __half* Abase = A  + (size_t)(m0 + tid) * K;
    const __half* Bbase = Wt + (size_t)(n0 + tid) * K;

    int wid = tid >> 5;
    int wm = (wid & 1) * 64;             // 2 warps m
    int wn = (wid >> 1) * 64;            // 2 warps n

    wmma::fragment<wmma::accumulator, 16, 16, 16, float> acc[4][4];
    #pragma unroll
    for (int i = 0; i < 4; i++)
        #pragma unroll
        for (int j = 0; j < 4; j++)
            wmma::fill_fragment(acc[i][j], 0.0f);

    const int nit = K / BKH;             // 24

    // Prologue: issue stages 0..STAGES-2
    #pragma unroll
    for (int s = 0; s < STAGES - 1; s++) {
        __half* a = hs + s * STAGE_H + tid * SSTRH;
        __half* b = a + BM * SSTRH;
        const __half* ag = Abase + s * BKH;
        const __half* bg = Bbase + s * BKH;
        #pragma unroll
        for (int c = 0; c < 4; c++) {
            cp_async16(a + c * 8, ag + c * 8);
            cp_async16(b + c * 8, bg + c * 8);
        }
        CP_COMMIT();
    }

    int sc_ = 0, sl_ = STAGES - 1;       // compute stage, next load stage
    for (int it = 0; it < nit; it++) {
        CP_WAIT_N(STAGES - 2);
        __syncthreads();

        // Refill stage sl_ (freed at it-1; safe after the barrier above)
        if (it + STAGES - 1 < nit) {
            __half* a = hs + sl_ * STAGE_H + tid * SSTRH;
            __half* b = a + BM * SSTRH;
            const __half* ag = Abase + (it + STAGES - 1) * BKH;
            const __half* bg = Bbase + (it + STAGES - 1) * BKH;
            #pragma unroll
            for (int c = 0; c < 4; c++) {
                cp_async16(a + c * 8, ag + c * 8);
                cp_async16(b + c * 8, bg + c * 8);
            }
        }
        CP_COMMIT();                     // keep group count consistent

        __half* Ac = hs + sc_ * STAGE_H;
        __half* Bc = Ac + BM * SSTRH;
        #pragma unroll
        for (int kk = 0; kk < BKH; kk += 16) {
            wmma::fragment<wmma::matrix_a, 16, 16, 16, __half, wmma::row_major> af[4];
            wmma::fragment<wmma::matrix_b, 16, 16, 16, __half, wmma::col_major> bf[4];
            #pragma unroll
            for (int i = 0; i < 4; i++)
                wmma::load_matrix_sync(af[i], &Ac[(wm + i * 16) * SSTRH + kk], SSTRH);
            #pragma unroll
            for (int j = 0; j < 4; j++)
                wmma::load_matrix_sync(bf[j], &Bc[(wn + j * 16) * SSTRH + kk], SSTRH);
            #pragma unroll
            for (int i = 0; i < 4; i++)
                #pragma unroll
                for (int j = 0; j < 4; j++)
                    wmma::mma_sync(acc[i][j], af[i], bf[j], acc[i][j]);
        }

        sc_ = (sc_ + 1 == STAGES) ? 0 : sc_ + 1;
        sl_ = (sl_ + 1 == STAGES) ? 0 : sl_ + 1;
    }
    CP_WAIT_N(0);
    __syncthreads();

    // Epilogue through shared (fp32)
    float* Cs = (float*)smem_raw;
    #pragma unroll
    for (int i = 0; i < 4; i++)
        #pragma unroll
        for (int j = 0; j < 4; j++)
            wmma::store_matrix_sync(&Cs[(wm + i * 16) * LDC + wn + j * 16],
                                    acc[i][j], LDC, wmma::mem_row_major);
    __syncthreads();

    #pragma unroll
    for (int i = 0; i < 32; i++) {
        int idx = tid + i * NTHR;
        int r = idx >> 5, c4 = idx & 31;
        const float* cs = &Cs[r * LDC + c4 * 4];
        float4 bv = *(const float4*)(bias + n0 + c4 * 4);
        float4 v;
        v.x = cs[0] + bv.x; v.y = cs[1] + bv.y;
        v.z = cs[2] + bv.z; v.w = cs[3] + bv.w;
        size_t g = (size_t)(m0 + r) * N + n0 + c4 * 4;
        if (RES) {
            float4 rv = *(const float4*)(res + g);
            v.x += rv.x; v.y += rv.y; v.z += rv.z; v.w += rv.w;
        }
        *(float4*)(Cout + g) = v;
    }
}

// ---------------------------------------------------------------------------
// Attention over time axis: one warp per (b,h,w,head) unit. T=16, HD=64.
// ---------------------------------------------------------------------------
#define QSTR 68
__global__ void attn_kernel(const float* __restrict__ qkv, float* __restrict__ o) {
    int warp_in_blk = threadIdx.x >> 5;
    int lane = threadIdx.x & 31;
    int unit = blockIdx.x * 2 + warp_in_blk;   // 2 warps per block

    __shared__ float sm[2][3 * 16 * QSTR + 256];
    float* q = sm[warp_in_blk];
    float* k = q + 16 * QSTR;
    float* v = k + 16 * QSTR;
    float* p = v + 16 * QSTR;                  // 16x16 probs

    int head = unit % NHh;
    int s = unit / NHh;
    int w = s & 31; s >>= 5;
    int h = s & 31;
    int b = s >> 5;

    int spatial = h * 32 + w;
    int fofs = head * 192;

    // Load q,k,v (T=16 x HD=64 each)
    for (int idx = lane; idx < 16 * 64; idx += 32) {
        int t = idx >> 6, d = idx & 63;
        size_t g = (size_t)((b * 16 + t) * 1024 + spatial) * F3 + fofs + d;
        q[t * QSTR + d] = qkv[g];
        k[t * QSTR + d] = qkv[g + 64];
        v[t * QSTR + d] = qkv[g + 128];
    }
    __syncwarp();

    // Scores: lane pair (2 lanes per tq), each lane does 8 tk
    int tq = lane >> 1;
    int tk0 = (lane & 1) * 8;
    float sc[8];
    #pragma unroll
    for (int j = 0; j < 8; j++) {
        float acc = 0.f;
        #pragma unroll
        for (int d = 0; d < 64; d++)
            acc += q[tq * QSTR + d] * k[(tk0 + j) * QSTR + d];
        sc[j] = acc * 0.125f;   // 1/sqrt(64)
    }
    float m = sc[0];
    #pragma unroll
    for (int j = 1; j < 8; j++) m = fmaxf(m, sc[j]);
    m = fmaxf(m, __shfl_xor_sync(0xffffffffu, m, 1));
    float sum = 0.f;
    #pragma unroll
    for (int j = 0; j < 8; j++) { sc[j] = __expf(sc[j] - m); sum += sc[j]; }
    sum += __shfl_xor_sync(0xffffffffu, sum, 1);
    float inv = 1.0f / sum;
    #pragma unroll
    for (int j = 0; j < 8; j++) p[tq * 16 + tk0 + j] = sc[j] * inv;
    __syncwarp();

    // o[t,d] = sum_tk p[t,tk] * v[tk,d]
    for (int idx = lane; idx < 16 * 64; idx += 32) {
        int t = idx >> 6, d = idx & 63;
        float acc = 0.f;
        #pragma unroll
        for (int tk = 0; tk < 16; tk++)
            acc += p[t * 16 + tk] * v[tk * QSTR + d];
        size_t g = (size_t)((b * 16 + t) * 1024 + spatial) * Cc + head * 64 + d;
        o[g] = acc;
    }
}

// ---------------------------------------------------------------------------
// Launch
// ---------------------------------------------------------------------------
extern "C" void kernel_launch(void* const* d_in, const int* in_sizes, int n_in,
                              void* d_out, int out_size) {
    const float* x     = (const float*)d_in[0];
    const float* ln1_w = (const float*)d_in[1];
    const float* ln1_b = (const float*)d_in[2];
    const float* Wqkv  = (const float*)d_in[3];
    const float* bqkv  = (const float*)d_in[4];
    const float* ln2_w = (const float*)d_in[5];
    const float* ln2_b = (const float*)d_in[6];
    const float* Wout  = (const float*)d_in[7];
    const float* bout  = (const float*)d_in[8];
    float* out = (float*)d_out;

    static __half *p_yh = nullptr, *p_wqh = nullptr, *p_woh = nullptr;
    static float *p_qkv = nullptr, *p_o = nullptr;
    if (!p_yh) {
        cudaGetSymbolAddress((void**)&p_yh, g_yh);
        cudaGetSymbolAddress((void**)&p_qkv, g_qkv);
        cudaGetSymbolAddress((void**)&p_o, g_o);
        cudaGetSymbolAddress((void**)&p_wqh, g_wqh);
        cudaGetSymbolAddress((void**)&p_woh, g_woh);
        cudaFuncSetAttribute(gemm_fp16<false>,
                             cudaFuncAttributeMaxDynamicSharedMemorySize, GEMM_SMEM_BYTES);
        cudaFuncSetAttribute(gemm_fp16<true>,
                             cudaFuncAttributeMaxDynamicSharedMemorySize, GEMM_SMEM_BYTES);
    }

    // 0) weights -> half
    {
        int n4q = (F3 * Cc) / 4, n4o = (Cc * Cc) / 4;
        f2h_kernel<<<(n4q + 255) / 256, 256>>>(Wqkv, p_wqh, n4q);
        f2h_kernel<<<(n4o + 255) / 256, 256>>>(Wout, p_woh, n4o);
    }

    // 1) LN1 -> half
    ln_kernel<<<NTOK, 192>>>(x, ln1_w, ln1_b, p_yh);

    // 2) QKV GEMM: (32768 x 2304)
    {
        dim3 grid(F3 / BN, NTOK / BM);     // 18 x 256
        gemm_fp16<false><<<grid, NTHR, GEMM_SMEM_BYTES>>>(p_yh, p_wqh, bqkv,
                                                          nullptr, p_qkv, F3, Cc);
    }

    // 3) Attention over time, per (b,h,w,head)
    {
        int nunits = Bb * Hh * Ww * NHh;   // 24576
        attn_kernel<<<nunits / 2, 64>>>(p_qkv, p_o);
    }

    // 4) LN2 -> half
    ln_kernel<<<NTOK, 192>>>(p_o, ln2_w, ln2_b, p_yh);

    // 5) Out GEMM + bias + residual: (32768 x 768)
    {
        dim3 grid(Cc / BN, NTOK / BM);     // 6 x 256
        gemm_fp16<true><<<grid, NTHR, GEMM_SMEM_BYTES>>>(p_yh, p_woh, bout,
                                                         x, out, Cc, Cc);
    }
}

// round 10
// speedup vs baseline: 1.0672x; 1.0672x over previous
#include <cuda_runtime.h>
#include <cstdint>
#include <cuda_fp16.h>
#include <mma.h>
using namespace nvcuda;

// Problem constants
#define Bb 2
#define Tt 16
#define Hh 32
#define Ww 32
#define Cc 768
#define NHh 12
#define HDd 64
#define NTOK (Bb*Tt*Hh*Ww)      // 32768
#define F3 (3*Cc)               // 2304

// Scratch (no allocations allowed — device globals)
__device__ __half g_yh[NTOK * Cc];      // LN output (half)
__device__ __half g_qkvh[NTOK * F3];    // QKV GEMM output (half)
__device__ __half g_wqh[F3 * Cc];       // half Wqkv
__device__ __half g_woh[Cc * Cc];       // half Wout

// ---------------------------------------------------------------------------
// float -> half conversion pre-pass
// ---------------------------------------------------------------------------
__global__ void f2h_kernel(const float* __restrict__ in,
                           __half* __restrict__ out, int n4) {
    int i = blockIdx.x * 256 + threadIdx.x;
    if (i < n4) {
        float4 v = ((const float4*)in)[i];
        ((__half2*)out)[2 * i]     = __floats2half2_rn(v.x, v.y);
        ((__half2*)out)[2 * i + 1] = __floats2half2_rn(v.z, v.w);
    }
}

// ---------------------------------------------------------------------------
// LayerNorm: one block (192 threads) per token; output in fp16
// ---------------------------------------------------------------------------
__global__ void ln_kernel(const float* __restrict__ x,
                          const float* __restrict__ w,
                          const float* __restrict__ b,
                          __half* __restrict__ y) {
    int tok = blockIdx.x;
    int t = threadIdx.x;
    const float4* xr = (const float4*)(x + (size_t)tok * Cc);
    __half2* yr = (__half2*)(y + (size_t)tok * Cc);

    float4 v = xr[t];
    float s  = v.x + v.y + v.z + v.w;
    float ss = v.x*v.x + v.y*v.y + v.z*v.z + v.w*v.w;

    __shared__ float reds[6], redss[6];
    #pragma unroll
    for (int o = 16; o; o >>= 1) {
        s  += __shfl_xor_sync(0xffffffffu, s,  o);
        ss += __shfl_xor_sync(0xffffffffu, ss, o);
    }
    int wid = t >> 5, lid = t & 31;
    if (lid == 0) { reds[wid] = s; redss[wid] = ss; }
    __syncthreads();
    if (t < 32) {
        s  = (lid < 6) ? reds[lid]  : 0.f;
        ss = (lid < 6) ? redss[lid] : 0.f;
        #pragma unroll
        for (int o = 4; o; o >>= 1) {
            s  += __shfl_xor_sync(0xffffffffu, s,  o);
            ss += __shfl_xor_sync(0xffffffffu, ss, o);
        }
        if (lid == 0) { reds[0] = s; redss[0] = ss; }
    }
    __syncthreads();
    float mu  = reds[0] * (1.0f / Cc);
    float var = redss[0] * (1.0f / Cc) - mu * mu;
    float rstd = rsqrtf(var + 1e-5f);

    float4 wv = ((const float4*)w)[t];
    float4 bv = ((const float4*)b)[t];
    float rx = (v.x - mu) * rstd * wv.x + bv.x;
    float ry = (v.y - mu) * rstd * wv.y + bv.y;
    float rz = (v.z - mu) * rstd * wv.z + bv.z;
    float rw = (v.w - mu) * rstd * wv.w + bv.w;
    yr[2 * t]     = __floats2half2_rn(rx, ry);
    yr[2 * t + 1] = __floats2half2_rn(rz, rw);
}

// ---------------------------------------------------------------------------
// FP16 wmma GEMM (fp32 accumulate), 3-stage cp.async, 1 barrier/iter.
// Block 128x128, 8 warps (2m x 4n), warp tile 64x32.  (round-8 config)
// OUTH: write __half output; RES: add fp32 residual (only with float output).
// ---------------------------------------------------------------------------
#define BM 128
#define BN 128
#define BKH 32
#define SSTRH 40
#define LDC 132
#define STAGES 3
#define NTHR 256
#define STAGE_H ((BM + BN) * SSTRH)            // 10240 halfs = 20480 B
#define PIPE_BYTES (STAGES * STAGE_H * 2)      // 61440
#define EPI_BYTES (BM * LDC * 4)               // 67584
#define GEMM_SMEM_BYTES (EPI_BYTES > PIPE_BYTES ? EPI_BYTES : PIPE_BYTES)

__device__ __forceinline__ void cp_async16(void* smem_dst, const void* gmem_src) {
    unsigned s = (unsigned)__cvta_generic_to_shared(smem_dst);
    asm volatile("cp.async.cg.shared.global [%0], [%1], 16;\n" :: "r"(s), "l"(gmem_src));
}
#define CP_COMMIT() asm volatile("cp.async.commit_group;\n" ::: "memory")
#define CP_WAIT_N(n) asm volatile("cp.async.wait_group %0;\n" :: "n"(n) : "memory")

template <bool RES, bool OUTH>
__global__ void __launch_bounds__(NTHR, 2) gemm_fp16(
        const __half* __restrict__ A,
        const __half* __restrict__ Wt,
        const float* __restrict__ bias,
        const float* __restrict__ res,
        float* __restrict__ Cout,
        __half* __restrict__ CoutH,
        int N, int K) {
    extern __shared__ __align__(16) char smem_raw[];
    __half* hs = (__half*)smem_raw;

    int tid = threadIdx.x;
    int m0 = blockIdx.y * BM;
    int n0 = blockIdx.x * BN;

    // load mapping: 2 threads per row, 2 x 16B chunks each
    int lrow = tid >> 1;
    int lc0  = (tid & 1) * 2;

    const __half* Abase = A  + (size_t)(m0 + lrow) * K + lc0 * 8;
    const __half* Bbase = Wt + (size_t)(n0 + lrow) * K + lc0 * 8;

    int wid = tid >> 5;
    int wm = (wid & 1) * 64;             // 2 warps m
    int wn = (wid >> 1) * 32;            // 4 warps n

    wmma::fragment<wmma::accumulator, 16, 16, 16, float> acc[4][2];
    #pragma unroll
    for (int i = 0; i < 4; i++)
        #pragma unroll
        for (int j = 0; j < 2; j++)
            wmma::fill_fragment(acc[i][j], 0.0f);

    const int nit = K / BKH;             // 24

    #pragma unroll
    for (int s = 0; s < STAGES - 1; s++) {
        __half* a = hs + s * STAGE_H + lrow * SSTRH + lc0 * 8;
        __half* b = hs + s * STAGE_H + BM * SSTRH + lrow * SSTRH + lc0 * 8;
        const __half* ag = Abase + s * BKH;
        const __half* bg = Bbase + s * BKH;
        #pragma unroll
        for (int c = 0; c < 2; c++) {
            cp_async16(a + c * 8, ag + c * 8);
            cp_async16(b + c * 8, bg + c * 8);
        }
        CP_COMMIT();
    }

    int sc_ = 0, sl_ = STAGES - 1;
    for (int it = 0; it < nit; it++) {
        CP_WAIT_N(STAGES - 2);
        __syncthreads();

        if (it + STAGES - 1 < nit) {
            __half* a = hs + sl_ * STAGE_H + lrow * SSTRH + lc0 * 8;
            __half* b = hs + sl_ * STAGE_H + BM * SSTRH + lrow * SSTRH + lc0 * 8;
            const __half* ag = Abase + (it + STAGES - 1) * BKH;
            const __half* bg = Bbase + (it + STAGES - 1) * BKH;
            #pragma unroll
            for (int c = 0; c < 2; c++) {
                cp_async16(a + c * 8, ag + c * 8);
                cp_async16(b + c * 8, bg + c * 8);
            }
        }
        CP_COMMIT();

        __half* Ac = hs + sc_ * STAGE_H;
        __half* Bc = Ac + BM * SSTRH;
        #pragma unroll
        for (int kk = 0; kk < BKH; kk += 16) {
            wmma::fragment<wmma::matrix_a, 16, 16, 16, __half, wmma::row_major> af[4];
            wmma::fragment<wmma::matrix_b, 16, 16, 16, __half, wmma::col_major> bf[2];
            #pragma unroll
            for (int i = 0; i < 4; i++)
                wmma::load_matrix_sync(af[i], &Ac[(wm + i * 16) * SSTRH + kk], SSTRH);
            #pragma unroll
            for (int j = 0; j < 2; j++)
                wmma::load_matrix_sync(bf[j], &Bc[(wn + j * 16) * SSTRH + kk], SSTRH);
            #pragma unroll
            for (int i = 0; i < 4; i++)
                #pragma unroll
                for (int j = 0; j < 2; j++)
                    wmma::mma_sync(acc[i][j], af[i], bf[j], acc[i][j]);
        }

        sc_ = (sc_ + 1 == STAGES) ? 0 : sc_ + 1;
        sl_ = (sl_ + 1 == STAGES) ? 0 : sl_ + 1;
    }
    CP_WAIT_N(0);
    __syncthreads();

    // Epilogue through shared (fp32)
    float* Cs = (float*)smem_raw;
    #pragma unroll
    for (int i = 0; i < 4; i++)
        #pragma unroll
        for (int j = 0; j < 2; j++)
            wmma::store_matrix_sync(&Cs[(wm + i * 16) * LDC + wn + j * 16],
                                    acc[i][j], LDC, wmma::mem_row_major);
    __syncthreads();

    if (OUTH) {
        // 128x128 tile as 8192 half2; 32 iters of 256 threads
        #pragma unroll
        for (int i = 0; i < 32; i++) {
            int idx = tid + i * NTHR;
            int r = idx >> 6, c2 = idx & 63;
            float2 cs = *(const float2*)&Cs[r * LDC + c2 * 2];
            float2 bv = *(const float2*)(bias + n0 + c2 * 2);
            __half2 hv = __floats2half2_rn(cs.x + bv.x, cs.y + bv.y);
            *((__half2*)(CoutH + (size_t)(m0 + r) * N + n0) + c2) = hv;
        }
    } else {
        #pragma unroll
        for (int i = 0; i < 16; i++) {
            int idx = tid + i * NTHR;
            int r = idx >> 5, c4 = idx & 31;
            const float* cs = &Cs[r * LDC + c4 * 4];
            float4 bv = *(const float4*)(bias + n0 + c4 * 4);
            float4 v;
            v.x = cs[0] + bv.x; v.y = cs[1] + bv.y;
            v.z = cs[2] + bv.z; v.w = cs[3] + bv.w;
            size_t g = (size_t)(m0 + r) * N + n0 + c4 * 4;
            if (RES) {
                float4 rv = *(const float4*)(res + g);
                v.x += rv.x; v.y += rv.y; v.z += rv.z; v.w += rv.w;
            }
            *(float4*)(Cout + g) = v;
        }
    }
}

// ---------------------------------------------------------------------------
// Fused attention + LayerNorm2.
// One block per (b,h,w): 12 warps, one per head. T=16, HD=64.
// Reads half qkv; writes half y (LN2 applied). Softmax/accum in fp32.
// ---------------------------------------------------------------------------
#define AT_THREADS 384
// smem layout (bytes):
#define QS_OFF 0
#define KS_OFF (12*16*36)                 // in half2 units
#define VS_OFF (2*12*16*36)
#define SM_H2  (3*12*16*36)               // 20736 half2 = 82944 B
#define PS_F   (12*16*17)                 // 3264 floats
#define OB_F2  (16*388)                   // 6208 float2
#define ATTN_SMEM_BYTES (SM_H2*4 + PS_F*4 + OB_F2*8 + (2*12*16 + 32)*4)

__global__ void __launch_bounds__(AT_THREADS) attn_ln2_kernel(
        const __half* __restrict__ qkv,
        const float* __restrict__ ln2w,
        const float* __restrict__ ln2b,
        __half* __restrict__ y) {
    extern __shared__ __align__(16) char sm_raw[];
    __half2* qs = (__half2*)sm_raw;               // [12][16][36]
    __half2* ks = qs + KS_OFF;
    __half2* vs = qs + VS_OFF;
    float* ps    = (float*)(qs + SM_H2);          // [12][16][17]
    float2* obuf = (float2*)(ps + PS_F);          // [16][388]  (776 floats/row)
    float* psum  = (float*)(obuf + OB_F2);        // [12][16]
    float* psq   = psum + 12*16;
    float* mus   = psq + 12*16;                   // [16]
    float* rstds = mus + 16;                      // [16]

    int tid = threadIdx.x;
    int h = tid >> 5;        // head (warp)
    int lane = tid & 31;
    int sp = blockIdx.x;     // b*1024 + spatial
    int b = sp >> 10;
    int spatial = sp & 1023;

    // Stage q,k,v for this head (16 rows x 32 half2 each)
    for (int i = lane; i < 16 * 32; i += 32) {
        int t = i >> 5, d2 = i & 31;
        size_t g = ((size_t)((b * 16 + t) * 1024 + spatial)) * F3 + h * 192;
        const __half2* p2 = (const __half2*)(qkv + g);
        qs[(h * 16 + t) * 36 + d2] = p2[d2];
        ks[(h * 16 + t) * 36 + d2] = p2[32 + d2];
        vs[(h * 16 + t) * 36 + d2] = p2[64 + d2];
    }
    __syncwarp();

    // Scores: lane pair per tq; each lane 8 tk
    int tq = lane >> 1;
    int tk0 = (lane & 1) * 8;
    __half2 qreg[32];
    #pragma unroll
    for (int d2 = 0; d2 < 32; d2++) qreg[d2] = qs[(h * 16 + tq) * 36 + d2];

    float sc[8];
    #pragma unroll
    for (int j = 0; j < 8; j++) {
        float acc = 0.f;
        #pragma unroll
        for (int d2 = 0; d2 < 32; d2++) {
            float2 qf = __half22float2(qreg[d2]);
            float2 kf = __half22float2(ks[(h * 16 + tk0 + j) * 36 + d2]);
            acc += qf.x * kf.x + qf.y * kf.y;
        }
        sc[j] = acc * 0.125f;
    }
    float m = sc[0];
    #pragma unroll
    for (int j = 1; j < 8; j++) m = fmaxf(m, sc[j]);
    m = fmaxf(m, __shfl_xor_sync(0xffffffffu, m, 1));
    float sum = 0.f;
    #pragma unroll
    for (int j = 0; j < 8; j++) { sc[j] = __expf(sc[j] - m); sum += sc[j]; }
    sum += __shfl_xor_sync(0xffffffffu, sum, 1);
    float inv = 1.0f / sum;
    #pragma unroll
    for (int j = 0; j < 8; j++) ps[(h * 16 + tq) * 17 + tk0 + j] = sc[j] * inv;
    __syncwarp();

    // o[t, :] for this head: per t, lane owns d-pair = lane. Also sum/sumsq.
    for (int t = 0; t < 16; t++) {
        float2 acc = make_float2(0.f, 0.f);
        #pragma unroll
        for (int tk = 0; tk < 16; tk++) {
            float p = ps[(h * 16 + t) * 17 + tk];
            float2 vf = __half22float2(vs[(h * 16 + tk) * 36 + lane]);
            acc.x += p * vf.x;
            acc.y += p * vf.y;
        }
        obuf[t * 388 + h * 32 + lane] = acc;
        float s  = acc.x + acc.y;
        float ss = acc.x * acc.x + acc.y * acc.y;
        #pragma unroll
        for (int o = 16; o; o >>= 1) {
            s  += __shfl_xor_sync(0xffffffffu, s,  o);
            ss += __shfl_xor_sync(0xffffffffu, ss, o);
        }
        if (lane == 0) { psum[h * 16 + t] = s; psq[h * 16 + t] = ss; }
    }
    __syncthreads();

    // LN2 stats per token
    if (tid < 16) {
        float s = 0.f, ss = 0.f;
        #pragma unroll
        for (int hh = 0; hh < 12; hh++) {
            s  += psum[hh * 16 + tid];
            ss += psq[hh * 16 + tid];
        }
        float mu = s * (1.0f / Cc);
        float var = ss * (1.0f / Cc) - mu * mu;
        mus[tid] = mu;
        rstds[tid] = rsqrtf(var + 1e-5f);
    }
    __syncthreads();

    // Normalize + write half y
    for (int idx = tid; idx < 16 * 384; idx += AT_THREADS) {
        int t = idx / 384, c2 = idx % 384;
        float mu = mus[t], rs = rstds[t];
        float2 o2 = obuf[t * 388 + c2];
        float2 w2 = *(const float2*)(ln2w + c2 * 2);
        float2 b2 = *(const float2*)(ln2b + c2 * 2);
        float r0 = (o2.x - mu) * rs * w2.x + b2.x;
        float r1 = (o2.y - mu) * rs * w2.y + b2.y;
        size_t g = ((size_t)((b * 16 + t) * 1024 + spatial)) * Cc + c2 * 2;
        *((__half2*)(y + g)) = __floats2half2_rn(r0, r1);
    }
}

// ---------------------------------------------------------------------------
// Launch
// ---------------------------------------------------------------------------
extern "C" void kernel_launch(void* const* d_in, const int* in_sizes, int n_in,
                              void* d_out, int out_size) {
    const float* x     = (const float*)d_in[0];
    const float* ln1_w = (const float*)d_in[1];
    const float* ln1_b = (const float*)d_in[2];
    const float* Wqkv  = (const float*)d_in[3];
    const float* bqkv  = (const float*)d_in[4];
    const float* ln2_w = (const float*)d_in[5];
    const float* ln2_b = (const float*)d_in[6];
    const float* Wout  = (const float*)d_in[7];
    const float* bout  = (const float*)d_in[8];
    float* out = (float*)d_out;

    static __half *p_yh = nullptr, *p_qkvh = nullptr, *p_wqh = nullptr,
                  *p_woh = nullptr;
    if (!p_yh) {
        cudaGetSymbolAddress((void**)&p_yh, g_yh);
        cudaGetSymbolAddress((void**)&p_qkvh, g_qkvh);
        cudaGetSymbolAddress((void**)&p_wqh, g_wqh);
        cudaGetSymbolAddress((void**)&p_woh, g_woh);
        cudaFuncSetAttribute((const void*)gemm_fp16<false, true>,
                             cudaFuncAttributeMaxDynamicSharedMemorySize, GEMM_SMEM_BYTES);
        cudaFuncSetAttribute((const void*)gemm_fp16<true, false>,
                             cudaFuncAttributeMaxDynamicSharedMemorySize, GEMM_SMEM_BYTES);
        cudaFuncSetAttribute((const void*)attn_ln2_kernel,
                             cudaFuncAttributeMaxDynamicSharedMemorySize, ATTN_SMEM_BYTES);
    }

    // 0) weights -> half
    {
        int n4q = (F3 * Cc) / 4, n4o = (Cc * Cc) / 4;
        f2h_kernel<<<(n4q + 255) / 256, 256>>>(Wqkv, p_wqh, n4q);
        f2h_kernel<<<(n4o + 255) / 256, 256>>>(Wout, p_woh, n4o);
    }

    // 1) LN1 -> half
    ln_kernel<<<NTOK, 192>>>(x, ln1_w, ln1_b, p_yh);

    // 2) QKV GEMM (half output): (32768 x 2304)
    {
        dim3 grid(F3 / BN, NTOK / BM);     // 18 x 256
        gemm_fp16<false, true><<<grid, NTHR, GEMM_SMEM_BYTES>>>(
            p_yh, p_wqh, bqkv, nullptr, nullptr, p_qkvh, F3, Cc);
    }

    // 3) Fused attention + LN2 -> half y
    {
        attn_ln2_kernel<<<Bb * Hh * Ww, AT_THREADS, ATTN_SMEM_BYTES>>>(
            p_qkvh, ln2_w, ln2_b, p_yh);
    }

    // 4) Out GEMM + bias + residual: (32768 x 768), float output
    {
        dim3 grid(Cc / BN, NTOK / BM);     // 6 x 256
        gemm_fp16<true, false><<<grid, NTHR, GEMM_SMEM_BYTES>>>(
            p_yh, p_woh, bout, x, out, nullptr, Cc, Cc);
    }
}

// round 11
// speedup vs baseline: 1.0931x; 1.0242x over previous
#include <cuda_runtime.h>
#include <cstdint>
#include <cuda_fp16.h>
#include <mma.h>
using namespace nvcuda;

// Problem constants
#define Bb 2
#define Tt 16
#define Hh 32
#define Ww 32
#define Cc 768
#define NHh 12
#define HDd 64
#define NTOK (Bb*Tt*Hh*Ww)      // 32768
#define F3 (3*Cc)               // 2304

// Scratch (no allocations allowed — device globals)
__device__ __half g_yh[NTOK * Cc];      // LN output (half)
__device__ __half g_qkvh[NTOK * F3];    // QKV GEMM output (half)
__device__ __half g_oh[NTOK * Cc];      // attention output (half)
__device__ __half g_wqh[F3 * Cc];       // half Wqkv
__device__ __half g_woh[Cc * Cc];       // half Wout

// ---------------------------------------------------------------------------
// float -> half conversion pre-pass
// ---------------------------------------------------------------------------
__global__ void f2h_kernel(const float* __restrict__ in,
                           __half* __restrict__ out, int n4) {
    int i = blockIdx.x * 256 + threadIdx.x;
    if (i < n4) {
        float4 v = ((const float4*)in)[i];
        ((__half2*)out)[2 * i]     = __floats2half2_rn(v.x, v.y);
        ((__half2*)out)[2 * i + 1] = __floats2half2_rn(v.z, v.w);
    }
}

// ---------------------------------------------------------------------------
// LayerNorm (float input): one block (192 threads) per token; half output
// ---------------------------------------------------------------------------
__global__ void ln_kernel(const float* __restrict__ x,
                          const float* __restrict__ w,
                          const float* __restrict__ b,
                          __half* __restrict__ y) {
    int tok = blockIdx.x;
    int t = threadIdx.x;
    const float4* xr = (const float4*)(x + (size_t)tok * Cc);
    __half2* yr = (__half2*)(y + (size_t)tok * Cc);

    float4 v = xr[t];
    float s  = v.x + v.y + v.z + v.w;
    float ss = v.x*v.x + v.y*v.y + v.z*v.z + v.w*v.w;

    __shared__ float reds[6], redss[6];
    #pragma unroll
    for (int o = 16; o; o >>= 1) {
        s  += __shfl_xor_sync(0xffffffffu, s,  o);
        ss += __shfl_xor_sync(0xffffffffu, ss, o);
    }
    int wid = t >> 5, lid = t & 31;
    if (lid == 0) { reds[wid] = s; redss[wid] = ss; }
    __syncthreads();
    if (t < 32) {
        s  = (lid < 6) ? reds[lid]  : 0.f;
        ss = (lid < 6) ? redss[lid] : 0.f;
        #pragma unroll
        for (int o = 4; o; o >>= 1) {
            s  += __shfl_xor_sync(0xffffffffu, s,  o);
            ss += __shfl_xor_sync(0xffffffffu, ss, o);
        }
        if (lid == 0) { reds[0] = s; redss[0] = ss; }
    }
    __syncthreads();
    float mu  = reds[0] * (1.0f / Cc);
    float var = redss[0] * (1.0f / Cc) - mu * mu;
    float rstd = rsqrtf(var + 1e-5f);

    float4 wv = ((const float4*)w)[t];
    float4 bv = ((const float4*)b)[t];
    float rx = (v.x - mu) * rstd * wv.x + bv.x;
    float ry = (v.y - mu) * rstd * wv.y + bv.y;
    float rz = (v.z - mu) * rstd * wv.z + bv.z;
    float rw = (v.w - mu) * rstd * wv.w + bv.w;
    yr[2 * t]     = __floats2half2_rn(rx, ry);
    yr[2 * t + 1] = __floats2half2_rn(rz, rw);
}

// ---------------------------------------------------------------------------
// LayerNorm (half input): one block (192 threads) per token; half output
// ---------------------------------------------------------------------------
__global__ void ln_h_kernel(const __half* __restrict__ x,
                            const float* __restrict__ w,
                            const float* __restrict__ b,
                            __half* __restrict__ y) {
    int tok = blockIdx.x;
    int t = threadIdx.x;
    const __half2* xr = (const __half2*)(x + (size_t)tok * Cc);
    __half2* yr = (__half2*)(y + (size_t)tok * Cc);

    float2 a = __half22float2(xr[2 * t]);
    float2 c = __half22float2(xr[2 * t + 1]);
    float s  = a.x + a.y + c.x + c.y;
    float ss = a.x*a.x + a.y*a.y + c.x*c.x + c.y*c.y;

    __shared__ float reds[6], redss[6];
    #pragma unroll
    for (int o = 16; o; o >>= 1) {
        s  += __shfl_xor_sync(0xffffffffu, s,  o);
        ss += __shfl_xor_sync(0xffffffffu, ss, o);
    }
    int wid = t >> 5, lid = t & 31;
    if (lid == 0) { reds[wid] = s; redss[wid] = ss; }
    __syncthreads();
    if (t < 32) {
        s  = (lid < 6) ? reds[lid]  : 0.f;
        ss = (lid < 6) ? redss[lid] : 0.f;
        #pragma unroll
        for (int o = 4; o; o >>= 1) {
            s  += __shfl_xor_sync(0xffffffffu, s,  o);
            ss += __shfl_xor_sync(0xffffffffu, ss, o);
        }
        if (lid == 0) { reds[0] = s; redss[0] = ss; }
    }
    __syncthreads();
    float mu  = reds[0] * (1.0f / Cc);
    float var = redss[0] * (1.0f / Cc) - mu * mu;
    float rstd = rsqrtf(var + 1e-5f);

    float4 wv = ((const float4*)w)[t];
    float4 bv = ((const float4*)b)[t];
    float rx = (a.x - mu) * rstd * wv.x + bv.x;
    float ry = (a.y - mu) * rstd * wv.y + bv.y;
    float rz = (c.x - mu) * rstd * wv.z + bv.z;
    float rw = (c.y - mu) * rstd * wv.w + bv.w;
    yr[2 * t]     = __floats2half2_rn(rx, ry);
    yr[2 * t + 1] = __floats2half2_rn(rz, rw);
}

// ---------------------------------------------------------------------------
// FP16 wmma GEMM (fp32 accumulate), 3-stage cp.async, 1 barrier/iter.
// Block 128x128, 8 warps (2m x 4n), warp tile 64x32. BK=64 halfs.
// ---------------------------------------------------------------------------
#define BM 128
#define BN 128
#define BKH 64
#define SSTRH 72
#define LDC 132
#define STAGES 3
#define NTHR 256
#define STAGE_H ((BM + BN) * SSTRH)            // 18432 halfs = 36864 B
#define PIPE_BYTES (STAGES * STAGE_H * 2)      // 110592
#define EPI_BYTES (BM * LDC * 4)               // 67584
#define GEMM_SMEM_BYTES (EPI_BYTES > PIPE_BYTES ? EPI_BYTES : PIPE_BYTES)

__device__ __forceinline__ void cp_async16(void* smem_dst, const void* gmem_src) {
    unsigned s = (unsigned)__cvta_generic_to_shared(smem_dst);
    asm volatile("cp.async.cg.shared.global [%0], [%1], 16;\n" :: "r"(s), "l"(gmem_src));
}
#define CP_COMMIT() asm volatile("cp.async.commit_group;\n" ::: "memory")
#define CP_WAIT_N(n) asm volatile("cp.async.wait_group %0;\n" :: "n"(n) : "memory")

template <bool RES, bool OUTH>
__global__ void __launch_bounds__(NTHR, 2) gemm_fp16(
        const __half* __restrict__ A,
        const __half* __restrict__ Wt,
        const float* __restrict__ bias,
        const float* __restrict__ res,
        float* __restrict__ Cout,
        __half* __restrict__ CoutH,
        int N, int K) {
    extern __shared__ __align__(16) char smem_raw[];
    __half* hs = (__half*)smem_raw;

    int tid = threadIdx.x;
    int m0 = blockIdx.y * BM;
    int n0 = blockIdx.x * BN;

    // load mapping: 2 threads per row; each owns 4 x 16B chunks (32 halfs)
    int lrow = tid >> 1;
    int lh0  = (tid & 1) * 32;           // half offset within row

    const __half* Abase = A  + (size_t)(m0 + lrow) * K + lh0;
    const __half* Bbase = Wt + (size_t)(n0 + lrow) * K + lh0;

    int wid = tid >> 5;
    int wm = (wid & 1) * 64;             // 2 warps m
    int wn = (wid >> 1) * 32;            // 4 warps n

    wmma::fragment<wmma::accumulator, 16, 16, 16, float> acc[4][2];
    #pragma unroll
    for (int i = 0; i < 4; i++)
        #pragma unroll
        for (int j = 0; j < 2; j++)
            wmma::fill_fragment(acc[i][j], 0.0f);

    const int nit = K / BKH;             // 12

    #pragma unroll
    for (int s = 0; s < STAGES - 1; s++) {
        __half* a = hs + s * STAGE_H + lrow * SSTRH + lh0;
        __half* b = a + BM * SSTRH;
        const __half* ag = Abase + s * BKH;
        const __half* bg = Bbase + s * BKH;
        #pragma unroll
        for (int c = 0; c < 4; c++) {
            cp_async16(a + c * 8, ag + c * 8);
            cp_async16(b + c * 8, bg + c * 8);
        }
        CP_COMMIT();
    }

    int sc_ = 0, sl_ = STAGES - 1;
    for (int it = 0; it < nit; it++) {
        CP_WAIT_N(STAGES - 2);
        __syncthreads();

        if (it + STAGES - 1 < nit) {
            __half* a = hs + sl_ * STAGE_H + lrow * SSTRH + lh0;
            __half* b = a + BM * SSTRH;
            const __half* ag = Abase + (it + STAGES - 1) * BKH;
            const __half* bg = Bbase + (it + STAGES - 1) * BKH;
            #pragma unroll
            for (int c = 0; c < 4; c++) {
                cp_async16(a + c * 8, ag + c * 8);
                cp_async16(b + c * 8, bg + c * 8);
            }
        }
        CP_COMMIT();

        __half* Ac = hs + sc_ * STAGE_H;
        __half* Bc = Ac + BM * SSTRH;
        #pragma unroll
        for (int kk = 0; kk < BKH; kk += 16) {
            wmma::fragment<wmma::matrix_a, 16, 16, 16, __half, wmma::row_major> af[4];
            wmma::fragment<wmma::matrix_b, 16, 16, 16, __half, wmma::col_major> bf[2];
            #pragma unroll
            for (int i = 0; i < 4; i++)
                wmma::load_matrix_sync(af[i], &Ac[(wm + i * 16) * SSTRH + kk], SSTRH);
            #pragma unroll
            for (int j = 0; j < 2; j++)
                wmma::load_matrix_sync(bf[j], &Bc[(wn + j * 16) * SSTRH + kk], SSTRH);
            #pragma unroll
            for (int i = 0; i < 4; i++)
                #pragma unroll
                for (int j = 0; j < 2; j++)
                    wmma::mma_sync(acc[i][j], af[i], bf[j], acc[i][j]);
        }

        sc_ = (sc_ + 1 == STAGES) ? 0 : sc_ + 1;
        sl_ = (sl_ + 1 == STAGES) ? 0 : sl_ + 1;
    }
    CP_WAIT_N(0);
    __syncthreads();

    // Epilogue through shared (fp32)
    float* Cs = (float*)smem_raw;
    #pragma unroll
    for (int i = 0; i < 4; i++)
        #pragma unroll
        for (int j = 0; j < 2; j++)
            wmma::store_matrix_sync(&Cs[(wm + i * 16) * LDC + wn + j * 16],
                                    acc[i][j], LDC, wmma::mem_row_major);
    __syncthreads();

    if (OUTH) {
        #pragma unroll
        for (int i = 0; i < 32; i++) {
            int idx = tid + i * NTHR;
            int r = idx >> 6, c2 = idx & 63;
            float2 cs = *(const float2*)&Cs[r * LDC + c2 * 2];
            float2 bv = *(const float2*)(bias + n0 + c2 * 2);
            __half2 hv = __floats2half2_rn(cs.x + bv.x, cs.y + bv.y);
            *((__half2*)(CoutH + (size_t)(m0 + r) * N + n0) + c2) = hv;
        }
    } else {
        #pragma unroll
        for (int i = 0; i < 16; i++) {
            int idx = tid + i * NTHR;
            int r = idx >> 5, c4 = idx & 31;
            const float* cs = &Cs[r * LDC + c4 * 4];
            float4 bv = *(const float4*)(bias + n0 + c4 * 4);
            float4 v;
            v.x = cs[0] + bv.x; v.y = cs[1] + bv.y;
            v.z = cs[2] + bv.z; v.w = cs[3] + bv.w;
            size_t g = (size_t)(m0 + r) * N + n0 + c4 * 4;
            if (RES) {
                float4 rv = *(const float4*)(res + g);
                v.x += rv.x; v.y += rv.y; v.z += rv.z; v.w += rv.w;
            }
            *(float4*)(Cout + g) = v;
        }
    }
}

// ---------------------------------------------------------------------------
// Attention over time axis: one warp per (b,h,w,head) unit. T=16, HD=64.
// Half input (qkv), half output (o). Softmax/accum in fp32.
// ---------------------------------------------------------------------------
__global__ void attn_kernel(const __half* __restrict__ qkv,
                            __half* __restrict__ o) {
    int warp_in_blk = threadIdx.x >> 5;
    int lane = threadIdx.x & 31;
    int unit = blockIdx.x * 2 + warp_in_blk;   // 2 warps per block

    __shared__ __half2 sh2[2][3 * 16 * 36];    // q,k,v per warp
    __shared__ float sp[2][16 * 17];           // probs per warp
    __half2* q = sh2[warp_in_blk];
    __half2* k = q + 16 * 36;
    __half2* v = k + 16 * 36;
    float* p = sp[warp_in_blk];

    int head = unit % NHh;
    int s = unit / NHh;
    int w = s & 31; s >>= 5;
    int h = s & 31;
    int b = s >> 5;

    int spatial = h * 32 + w;

    // Load q,k,v (16 rows x 32 half2 each)
    for (int i = lane; i < 16 * 32; i += 32) {
        int t = i >> 5, d2 = i & 31;
        size_t g = ((size_t)((b * 16 + t) * 1024 + spatial)) * F3 + head * 192;
        const __half2* p2 = (const __half2*)(qkv + g);
        q[t * 36 + d2] = p2[d2];
        k[t * 36 + d2] = p2[32 + d2];
        v[t * 36 + d2] = p2[64 + d2];
    }
    __syncwarp();

    // Scores: lane pair per tq; each lane 8 tk
    int tq = lane >> 1;
    int tk0 = (lane & 1) * 8;
    float sc[8];
    #pragma unroll
    for (int j = 0; j < 8; j++) {
        float acc = 0.f;
        #pragma unroll
        for (int d2 = 0; d2 < 32; d2++) {
            float2 qf = __half22float2(q[tq * 36 + d2]);
            float2 kf = __half22float2(k[(tk0 + j) * 36 + d2]);
            acc += qf.x * kf.x + qf.y * kf.y;
        }
        sc[j] = acc * 0.125f;
    }
    float m = sc[0];
    #pragma unroll
    for (int j = 1; j < 8; j++) m = fmaxf(m, sc[j]);
    m = fmaxf(m, __shfl_xor_sync(0xffffffffu, m, 1));
    float sum = 0.f;
    #pragma unroll
    for (int j = 0; j < 8; j++) { sc[j] = __expf(sc[j] - m); sum += sc[j]; }
    sum += __shfl_xor_sync(0xffffffffu, sum, 1);
    float inv = 1.0f / sum;
    #pragma unroll
    for (int j = 0; j < 8; j++) p[tq * 17 + tk0 + j] = sc[j] * inv;
    __syncwarp();

    // o[t, d2=lane]: loop t; accumulate over tk in fp32; write half2
    for (int t = 0; t < 16; t++) {
        float2 acc = make_float2(0.f, 0.f);
        #pragma unroll
        for (int tk = 0; tk < 16; tk++) {
            float pw = p[t * 17 + tk];
            float2 vf = __half22float2(v[tk * 36 + lane]);
            acc.x += pw * vf.x;
            acc.y += pw * vf.y;
        }
        size_t g = ((size_t)((b * 16 + t) * 1024 + spatial)) * Cc + head * 64;
        *((__half2*)(o + g) + lane) = __floats2half2_rn(acc.x, acc.y);
    }
}

// ---------------------------------------------------------------------------
// Launch
// ---------------------------------------------------------------------------
extern "C" void kernel_launch(void* const* d_in, const int* in_sizes, int n_in,
                              void* d_out, int out_size) {
    const float* x     = (const float*)d_in[0];
    const float* ln1_w = (const float*)d_in[1];
    const float* ln1_b = (const float*)d_in[2];
    const float* Wqkv  = (const float*)d_in[3];
    const float* bqkv  = (const float*)d_in[4];
    const float* ln2_w = (const float*)d_in[5];
    const float* ln2_b = (const float*)d_in[6];
    const float* Wout  = (const float*)d_in[7];
    const float* bout  = (const float*)d_in[8];
    float* out = (float*)d_out;

    static __half *p_yh = nullptr, *p_qkvh = nullptr, *p_oh = nullptr,
                  *p_wqh = nullptr, *p_woh = nullptr;
    if (!p_yh) {
        cudaGetSymbolAddress((void**)&p_yh, g_yh);
        cudaGetSymbolAddress((void**)&p_qkvh, g_qkvh);
        cudaGetSymbolAddress((void**)&p_oh, g_oh);
        cudaGetSymbolAddress((void**)&p_wqh, g_wqh);
        cudaGetSymbolAddress((void**)&p_woh, g_woh);
        cudaFuncSetAttribute((const void*)gemm_fp16<false, true>,
                             cudaFuncAttributeMaxDynamicSharedMemorySize, GEMM_SMEM_BYTES);
        cudaFuncSetAttribute((const void*)gemm_fp16<true, false>,
                             cudaFuncAttributeMaxDynamicSharedMemorySize, GEMM_SMEM_BYTES);
    }

    // 0) weights -> half
    {
        int n4q = (F3 * Cc) / 4, n4o = (Cc * Cc) / 4;
        f2h_kernel<<<(n4q + 255) / 256, 256>>>(Wqkv, p_wqh, n4q);
        f2h_kernel<<<(n4o + 255) / 256, 256>>>(Wout, p_woh, n4o);
    }

    // 1) LN1 -> half
    ln_kernel<<<NTOK, 192>>>(x, ln1_w, ln1_b, p_yh);

    // 2) QKV GEMM (half output): (32768 x 2304)
    {
        dim3 grid(F3 / BN, NTOK / BM);     // 18 x 256
        gemm_fp16<false, true><<<grid, NTHR, GEMM_SMEM_BYTES>>>(
            p_yh, p_wqh, bqkv, nullptr, nullptr, p_qkvh, F3, Cc);
    }

    // 3) Attention (half in/out)
    {
        int nunits = Bb * Hh * Ww * NHh;   // 24576
        attn_kernel<<<nunits / 2, 64>>>(p_qkvh, p_oh);
    }

    // 4) LN2 (half in) -> half y
    ln_h_kernel<<<NTOK, 192>>>(p_oh, ln2_w, ln2_b, p_yh);

    // 5) Out GEMM + bias + residual: (32768 x 768), float output
    {
        dim3 grid(Cc / BN, NTOK / BM);     // 6 x 256
        gemm_fp16<true, false><<<grid, NTHR, GEMM_SMEM_BYTES>>>(
            p_yh, p_woh, bout, x, out, nullptr, Cc, Cc);
    }
}

// round 12
// speedup vs baseline: 1.1933x; 1.0917x over previous
#include <cuda_runtime.h>
#include <cstdint>
#include <cuda_fp16.h>
#include <mma.h>
using namespace nvcuda;

// Problem constants
#define Bb 2
#define Tt 16
#define Hh 32
#define Ww 32
#define Cc 768
#define NHh 12
#define HDd 64
#define NTOK (Bb*Tt*Hh*Ww)      // 32768
#define F3 (3*Cc)               // 2304

// Scratch (no allocations allowed — device globals)
__device__ __half g_yh[NTOK * Cc];      // LN output (half)
__device__ __half g_qkvh[NTOK * F3];    // QKV GEMM output (half)
__device__ __half g_oh[NTOK * Cc];      // attention output (half)
__device__ __half g_wqh[F3 * Cc];       // half Wqkv
__device__ __half g_woh[Cc * Cc];       // half Wout

// ---------------------------------------------------------------------------
// float -> half conversion pre-pass
// ---------------------------------------------------------------------------
__global__ void f2h_kernel(const float* __restrict__ in,
                           __half* __restrict__ out, int n4) {
    int i = blockIdx.x * 256 + threadIdx.x;
    if (i < n4) {
        float4 v = ((const float4*)in)[i];
        ((__half2*)out)[2 * i]     = __floats2half2_rn(v.x, v.y);
        ((__half2*)out)[2 * i + 1] = __floats2half2_rn(v.z, v.w);
    }
}

// ---------------------------------------------------------------------------
// LayerNorm (float input): one block (192 threads) per token; half output
// ---------------------------------------------------------------------------
__global__ void ln_kernel(const float* __restrict__ x,
                          const float* __restrict__ w,
                          const float* __restrict__ b,
                          __half* __restrict__ y) {
    int tok = blockIdx.x;
    int t = threadIdx.x;
    const float4* xr = (const float4*)(x + (size_t)tok * Cc);
    __half2* yr = (__half2*)(y + (size_t)tok * Cc);

    float4 v = xr[t];
    float s  = v.x + v.y + v.z + v.w;
    float ss = v.x*v.x + v.y*v.y + v.z*v.z + v.w*v.w;

    __shared__ float reds[6], redss[6];
    #pragma unroll
    for (int o = 16; o; o >>= 1) {
        s  += __shfl_xor_sync(0xffffffffu, s,  o);
        ss += __shfl_xor_sync(0xffffffffu, ss, o);
    }
    int wid = t >> 5, lid = t & 31;
    if (lid == 0) { reds[wid] = s; redss[wid] = ss; }
    __syncthreads();
    if (t < 32) {
        s  = (lid < 6) ? reds[lid]  : 0.f;
        ss = (lid < 6) ? redss[lid] : 0.f;
        #pragma unroll
        for (int o = 4; o; o >>= 1) {
            s  += __shfl_xor_sync(0xffffffffu, s,  o);
            ss += __shfl_xor_sync(0xffffffffu, ss, o);
        }
        if (lid == 0) { reds[0] = s; redss[0] = ss; }
    }
    __syncthreads();
    float mu  = reds[0] * (1.0f / Cc);
    float var = redss[0] * (1.0f / Cc) - mu * mu;
    float rstd = rsqrtf(var + 1e-5f);

    float4 wv = ((const float4*)w)[t];
    float4 bv = ((const float4*)b)[t];
    float rx = (v.x - mu) * rstd * wv.x + bv.x;
    float ry = (v.y - mu) * rstd * wv.y + bv.y;
    float rz = (v.z - mu) * rstd * wv.z + bv.z;
    float rw = (v.w - mu) * rstd * wv.w + bv.w;
    yr[2 * t]     = __floats2half2_rn(rx, ry);
    yr[2 * t + 1] = __floats2half2_rn(rz, rw);
}

// ---------------------------------------------------------------------------
// LayerNorm (half input): one block (192 threads) per token; half output
// ---------------------------------------------------------------------------
__global__ void ln_h_kernel(const __half* __restrict__ x,
                            const float* __restrict__ w,
                            const float* __restrict__ b,
                            __half* __restrict__ y) {
    int tok = blockIdx.x;
    int t = threadIdx.x;
    const __half2* xr = (const __half2*)(x + (size_t)tok * Cc);
    __half2* yr = (__half2*)(y + (size_t)tok * Cc);

    float2 a = __half22float2(xr[2 * t]);
    float2 c = __half22float2(xr[2 * t + 1]);
    float s  = a.x + a.y + c.x + c.y;
    float ss = a.x*a.x + a.y*a.y + c.x*c.x + c.y*c.y;

    __shared__ float reds[6], redss[6];
    #pragma unroll
    for (int o = 16; o; o >>= 1) {
        s  += __shfl_xor_sync(0xffffffffu, s,  o);
        ss += __shfl_xor_sync(0xffffffffu, ss, o);
    }
    int wid = t >> 5, lid = t & 31;
    if (lid == 0) { reds[wid] = s; redss[wid] = ss; }
    __syncthreads();
    if (t < 32) {
        s  = (lid < 6) ? reds[lid]  : 0.f;
        ss = (lid < 6) ? redss[lid] : 0.f;
        #pragma unroll
        for (int o = 4; o; o >>= 1) {
            s  += __shfl_xor_sync(0xffffffffu, s,  o);
            ss += __shfl_xor_sync(0xffffffffu, ss, o);
        }
        if (lid == 0) { reds[0] = s; redss[0] = ss; }
    }
    __syncthreads();
    float mu  = reds[0] * (1.0f / Cc);
    float var = redss[0] * (1.0f / Cc) - mu * mu;
    float rstd = rsqrtf(var + 1e-5f);

    float4 wv = ((const float4*)w)[t];
    float4 bv = ((const float4*)b)[t];
    float rx = (a.x - mu) * rstd * wv.x + bv.x;
    float ry = (a.y - mu) * rstd * wv.y + bv.y;
    float rz = (c.x - mu) * rstd * wv.z + bv.z;
    float rw = (c.y - mu) * rstd * wv.w + bv.w;
    yr[2 * t]     = __floats2half2_rn(rx, ry);
    yr[2 * t + 1] = __floats2half2_rn(rz, rw);
}

// ---------------------------------------------------------------------------
// FP16 wmma GEMM (fp32 accumulate), 3-stage cp.async, 1 barrier/iter.
// Block 128x128, 8 warps (2m x 4n), warp tile 64x32. BK=32 halfs. (round-8 cfg)
// ---------------------------------------------------------------------------
#define BM 128
#define BN 128
#define BKH 32
#define SSTRH 40
#define LDC 132
#define STAGES 3
#define NTHR 256
#define STAGE_H ((BM + BN) * SSTRH)            // 10240 halfs = 20480 B
#define PIPE_BYTES (STAGES * STAGE_H * 2)      // 61440
#define EPI_BYTES (BM * LDC * 4)               // 67584
#define GEMM_SMEM_BYTES (EPI_BYTES > PIPE_BYTES ? EPI_BYTES : PIPE_BYTES)

__device__ __forceinline__ void cp_async16(void* smem_dst, const void* gmem_src) {
    unsigned s = (unsigned)__cvta_generic_to_shared(smem_dst);
    asm volatile("cp.async.cg.shared.global [%0], [%1], 16;\n" :: "r"(s), "l"(gmem_src));
}
#define CP_COMMIT() asm volatile("cp.async.commit_group;\n" ::: "memory")
#define CP_WAIT_N(n) asm volatile("cp.async.wait_group %0;\n" :: "n"(n) : "memory")

template <bool RES, bool OUTH>
__global__ void __launch_bounds__(NTHR, 2) gemm_fp16(
        const __half* __restrict__ A,
        const __half* __restrict__ Wt,
        const float* __restrict__ bias,
        const float* __restrict__ res,
        float* __restrict__ Cout,
        __half* __restrict__ CoutH,
        int N, int K) {
    extern __shared__ __align__(16) char smem_raw[];
    __half* hs = (__half*)smem_raw;

    int tid = threadIdx.x;
    int m0 = blockIdx.y * BM;
    int n0 = blockIdx.x * BN;

    // load mapping: 2 threads per row, 2 x 16B chunks each
    int lrow = tid >> 1;
    int lc0  = (tid & 1) * 2;

    const __half* Abase = A  + (size_t)(m0 + lrow) * K + lc0 * 8;
    const __half* Bbase = Wt + (size_t)(n0 + lrow) * K + lc0 * 8;

    int wid = tid >> 5;
    int wm = (wid & 1) * 64;             // 2 warps m
    int wn = (wid >> 1) * 32;            // 4 warps n

    wmma::fragment<wmma::accumulator, 16, 16, 16, float> acc[4][2];
    #pragma unroll
    for (int i = 0; i < 4; i++)
        #pragma unroll
        for (int j = 0; j < 2; j++)
            wmma::fill_fragment(acc[i][j], 0.0f);

    const int nit = K / BKH;             // 24

    #pragma unroll
    for (int s = 0; s < STAGES - 1; s++) {
        __half* a = hs + s * STAGE_H + lrow * SSTRH + lc0 * 8;
        __half* b = hs + s * STAGE_H + BM * SSTRH + lrow * SSTRH + lc0 * 8;
        const __half* ag = Abase + s * BKH;
        const __half* bg = Bbase + s * BKH;
        #pragma unroll
        for (int c = 0; c < 2; c++) {
            cp_async16(a + c * 8, ag + c * 8);
            cp_async16(b + c * 8, bg + c * 8);
        }
        CP_COMMIT();
    }

    int sc_ = 0, sl_ = STAGES - 1;
    for (int it = 0; it < nit; it++) {
        CP_WAIT_N(STAGES - 2);
        __syncthreads();

        if (it + STAGES - 1 < nit) {
            __half* a = hs + sl_ * STAGE_H + lrow * SSTRH + lc0 * 8;
            __half* b = hs + sl_ * STAGE_H + BM * SSTRH + lrow * SSTRH + lc0 * 8;
            const __half* ag = Abase + (it + STAGES - 1) * BKH;
            const __half* bg = Bbase + (it + STAGES - 1) * BKH;
            #pragma unroll
            for (int c = 0; c < 2; c++) {
                cp_async16(a + c * 8, ag + c * 8);
                cp_async16(b + c * 8, bg + c * 8);
            }
        }
        CP_COMMIT();

        __half* Ac = hs + sc_ * STAGE_H;
        __half* Bc = Ac + BM * SSTRH;
        #pragma unroll
        for (int kk = 0; kk < BKH; kk += 16) {
            wmma::fragment<wmma::matrix_a, 16, 16, 16, __half, wmma::row_major> af[4];
            wmma::fragment<wmma::matrix_b, 16, 16, 16, __half, wmma::col_major> bf[2];
            #pragma unroll
            for (int i = 0; i < 4; i++)
                wmma::load_matrix_sync(af[i], &Ac[(wm + i * 16) * SSTRH + kk], SSTRH);
            #pragma unroll
            for (int j = 0; j < 2; j++)
                wmma::load_matrix_sync(bf[j], &Bc[(wn + j * 16) * SSTRH + kk], SSTRH);
            #pragma unroll
            for (int i = 0; i < 4; i++)
                #pragma unroll
                for (int j = 0; j < 2; j++)
                    wmma::mma_sync(acc[i][j], af[i], bf[j], acc[i][j]);
        }

        sc_ = (sc_ + 1 == STAGES) ? 0 : sc_ + 1;
        sl_ = (sl_ + 1 == STAGES) ? 0 : sl_ + 1;
    }
    CP_WAIT_N(0);
    __syncthreads();

    // Epilogue through shared (fp32)
    float* Cs = (float*)smem_raw;
    #pragma unroll
    for (int i = 0; i < 4; i++)
        #pragma unroll
        for (int j = 0; j < 2; j++)
            wmma::store_matrix_sync(&Cs[(wm + i * 16) * LDC + wn + j * 16],
                                    acc[i][j], LDC, wmma::mem_row_major);
    __syncthreads();

    if (OUTH) {
        #pragma unroll
        for (int i = 0; i < 32; i++) {
            int idx = tid + i * NTHR;
            int r = idx >> 6, c2 = idx & 63;
            float2 cs = *(const float2*)&Cs[r * LDC + c2 * 2];
            float2 bv = *(const float2*)(bias + n0 + c2 * 2);
            __half2 hv = __floats2half2_rn(cs.x + bv.x, cs.y + bv.y);
            *((__half2*)(CoutH + (size_t)(m0 + r) * N + n0) + c2) = hv;
        }
    } else {
        #pragma unroll
        for (int i = 0; i < 16; i++) {
            int idx = tid + i * NTHR;
            int r = idx >> 5, c4 = idx & 31;
            const float* cs = &Cs[r * LDC + c4 * 4];
            float4 bv = *(const float4*)(bias + n0 + c4 * 4);
            float4 v;
            v.x = cs[0] + bv.x; v.y = cs[1] + bv.y;
            v.z = cs[2] + bv.z; v.w = cs[3] + bv.w;
            size_t g = (size_t)(m0 + r) * N + n0 + c4 * 4;
            if (RES) {
                float4 rv = *(const float4*)(res + g);
                v.x += rv.x; v.y += rv.y; v.z += rv.z; v.w += rv.w;
            }
            *(float4*)(Cout + g) = v;
        }
    }
}

// ---------------------------------------------------------------------------
// Attention over time axis: one warp per (b,h,w,head) unit. T=16, HD=64.
// Half input (qkv), half output (o). Softmax/accum in fp32.
// ---------------------------------------------------------------------------
__global__ void attn_kernel(const __half* __restrict__ qkv,
                            __half* __restrict__ o) {
    int warp_in_blk = threadIdx.x >> 5;
    int lane = threadIdx.x & 31;
    int unit = blockIdx.x * 2 + warp_in_blk;   // 2 warps per block

    __shared__ __half2 sh2[2][3 * 16 * 36];    // q,k,v per warp
    __shared__ float sp[2][16 * 17];           // probs per warp
    __half2* q = sh2[warp_in_blk];
    __half2* k = q + 16 * 36;
    __half2* v = k + 16 * 36;
    float* p = sp[warp_in_blk];

    int head = unit % NHh;
    int s = unit / NHh;
    int w = s & 31; s >>= 5;
    int h = s & 31;
    int b = s >> 5;

    int spatial = h * 32 + w;

    // Load q,k,v (16 rows x 32 half2 each)
    for (int i = lane; i < 16 * 32; i += 32) {
        int t = i >> 5, d2 = i & 31;
        size_t g = ((size_t)((b * 16 + t) * 1024 + spatial)) * F3 + head * 192;
        const __half2* p2 = (const __half2*)(qkv + g);
        q[t * 36 + d2] = p2[d2];
        k[t * 36 + d2] = p2[32 + d2];
        v[t * 36 + d2] = p2[64 + d2];
    }
    __syncwarp();

    // Scores: lane pair per tq; each lane 8 tk
    int tq = lane >> 1;
    int tk0 = (lane & 1) * 8;
    float sc[8];
    #pragma unroll
    for (int j = 0; j < 8; j++) {
        float acc = 0.f;
        #pragma unroll
        for (int d2 = 0; d2 < 32; d2++) {
            float2 qf = __half22float2(q[tq * 36 + d2]);
            float2 kf = __half22float2(k[(tk0 + j) * 36 + d2]);
            acc += qf.x * kf.x + qf.y * kf.y;
        }
        sc[j] = acc * 0.125f;
    }
    float m = sc[0];
    #pragma unroll
    for (int j = 1; j < 8; j++) m = fmaxf(m, sc[j]);
    m = fmaxf(m, __shfl_xor_sync(0xffffffffu, m, 1));
    float sum = 0.f;
    #pragma unroll
    for (int j = 0; j < 8; j++) { sc[j] = __expf(sc[j] - m); sum += sc[j]; }
    sum += __shfl_xor_sync(0xffffffffu, sum, 1);
    float inv = 1.0f / sum;
    #pragma unroll
    for (int j = 0; j < 8; j++) p[tq * 17 + tk0 + j] = sc[j] * inv;
    __syncwarp();

    // o[t, d2=lane]: loop t; accumulate over tk in fp32; write half2
    for (int t = 0; t < 16; t++) {
        float2 acc = make_float2(0.f, 0.f);
        #pragma unroll
        for (int tk = 0; tk < 16; tk++) {
            float pw = p[t * 17 + tk];
            float2 vf = __half22float2(v[tk * 36 + lane]);
            acc.x += pw * vf.x;
            acc.y += pw * vf.y;
        }
        size_t g = ((size_t)((b * 16 + t) * 1024 + spatial)) * Cc + head * 64;
        *((__half2*)(o + g) + lane) = __floats2half2_rn(acc.x, acc.y);
    }
}

// ---------------------------------------------------------------------------
// Launch
// ---------------------------------------------------------------------------
extern "C" void kernel_launch(void* const* d_in, const int* in_sizes, int n_in,
                              void* d_out, int out_size) {
    const float* x     = (const float*)d_in[0];
    const float* ln1_w = (const float*)d_in[1];
    const float* ln1_b = (const float*)d_in[2];
    const float* Wqkv  = (const float*)d_in[3];
    const float* bqkv  = (const float*)d_in[4];
    const float* ln2_w = (const float*)d_in[5];
    const float* ln2_b = (const float*)d_in[6];
    const float* Wout  = (const float*)d_in[7];
    const float* bout  = (const float*)d_in[8];
    float* out = (float*)d_out;

    static __half *p_yh = nullptr, *p_qkvh = nullptr, *p_oh = nullptr,
                  *p_wqh = nullptr, *p_woh = nullptr;
    if (!p_yh) {
        cudaGetSymbolAddress((void**)&p_yh, g_yh);
        cudaGetSymbolAddress((void**)&p_qkvh, g_qkvh);
        cudaGetSymbolAddress((void**)&p_oh, g_oh);
        cudaGetSymbolAddress((void**)&p_wqh, g_wqh);
        cudaGetSymbolAddress((void**)&p_woh, g_woh);
        cudaFuncSetAttribute((const void*)gemm_fp16<false, true>,
                             cudaFuncAttributeMaxDynamicSharedMemorySize, GEMM_SMEM_BYTES);
        cudaFuncSetAttribute((const void*)gemm_fp16<true, false>,
                             cudaFuncAttributeMaxDynamicSharedMemorySize, GEMM_SMEM_BYTES);
    }

    // 0) weights -> half
    {
        int n4q = (F3 * Cc) / 4, n4o = (Cc * Cc) / 4;
        f2h_kernel<<<(n4q + 255) / 256, 256>>>(Wqkv, p_wqh, n4q);
        f2h_kernel<<<(n4o + 255) / 256, 256>>>(Wout, p_woh, n4o);
    }

    // 1) LN1 -> half
    ln_kernel<<<NTOK, 192>>>(x, ln1_w, ln1_b, p_yh);

    // 2) QKV GEMM (half output): (32768 x 2304)
    {
        dim3 grid(F3 / BN, NTOK / BM);     // 18 x 256
        gemm_fp16<false, true><<<grid, NTHR, GEMM_SMEM_BYTES>>>(
            p_yh, p_wqh, bqkv, nullptr, nullptr, p_qkvh, F3, Cc);
    }

    // 3) Attention (half in/out)
    {
        int nunits = Bb * Hh * Ww * NHh;   // 24576
        attn_kernel<<<nunits / 2, 64>>>(p_qkvh, p_oh);
    }

    // 4) LN2 (half in) -> half y
    ln_h_kernel<<<NTOK, 192>>>(p_oh, ln2_w, ln2_b, p_yh);

    // 5) Out GEMM + bias + residual: (32768 x 768), float output
    {
        dim3 grid(Cc / BN, NTOK / BM);     // 6 x 256
        gemm_fp16<true, false><<<grid, NTHR, GEMM_SMEM_BYTES>>>(
            p_yh, p_woh, bout, x, out, nullptr, Cc, Cc);
    }
}

// round 13
// speedup vs baseline: 1.1965x; 1.0026x over previous
#include <cuda_runtime.h>
#include <cstdint>
#include <cuda_fp16.h>
#include <mma.h>
using namespace nvcuda;

// Problem constants
#define Bb 2
#define Tt 16
#define Hh 32
#define Ww 32
#define Cc 768
#define NHh 12
#define HDd 64
#define NTOK (Bb*Tt*Hh*Ww)      // 32768
#define F3 (3*Cc)               // 2304

// Scratch (no allocations allowed — device globals)
__device__ __half g_yh[NTOK * Cc];      // LN output (half)
__device__ __half g_qkvh[NTOK * F3];    // QKV GEMM output (half)
__device__ __half g_oh[NTOK * Cc];      // attention output (half)
__device__ __half g_wqh[F3 * Cc];       // half Wqkv
__device__ __half g_woh[Cc * Cc];       // half Wout

// ---------------------------------------------------------------------------
// float -> half conversion pre-pass
// ---------------------------------------------------------------------------
__global__ void f2h_kernel(const float* __restrict__ in,
                           __half* __restrict__ out, int n4) {
    int i = blockIdx.x * 256 + threadIdx.x;
    if (i < n4) {
        float4 v = ((const float4*)in)[i];
        ((__half2*)out)[2 * i]     = __floats2half2_rn(v.x, v.y);
        ((__half2*)out)[2 * i + 1] = __floats2half2_rn(v.z, v.w);
    }
}

// ---------------------------------------------------------------------------
// LayerNorm (float input): one block (192 threads) per token; half output
// ---------------------------------------------------------------------------
__global__ void ln_kernel(const float* __restrict__ x,
                          const float* __restrict__ w,
                          const float* __restrict__ b,
                          __half* __restrict__ y) {
    int tok = blockIdx.x;
    int t = threadIdx.x;
    const float4* xr = (const float4*)(x + (size_t)tok * Cc);
    __half2* yr = (__half2*)(y + (size_t)tok * Cc);

    float4 v = xr[t];
    float s  = v.x + v.y + v.z + v.w;
    float ss = v.x*v.x + v.y*v.y + v.z*v.z + v.w*v.w;

    __shared__ float reds[6], redss[6];
    #pragma unroll
    for (int o = 16; o; o >>= 1) {
        s  += __shfl_xor_sync(0xffffffffu, s,  o);
        ss += __shfl_xor_sync(0xffffffffu, ss, o);
    }
    int wid = t >> 5, lid = t & 31;
    if (lid == 0) { reds[wid] = s; redss[wid] = ss; }
    __syncthreads();
    if (t < 32) {
        s  = (lid < 6) ? reds[lid]  : 0.f;
        ss = (lid < 6) ? redss[lid] : 0.f;
        #pragma unroll
        for (int o = 4; o; o >>= 1) {
            s  += __shfl_xor_sync(0xffffffffu, s,  o);
            ss += __shfl_xor_sync(0xffffffffu, ss, o);
        }
        if (lid == 0) { reds[0] = s; redss[0] = ss; }
    }
    __syncthreads();
    float mu  = reds[0] * (1.0f / Cc);
    float var = redss[0] * (1.0f / Cc) - mu * mu;
    float rstd = rsqrtf(var + 1e-5f);

    float4 wv = ((const float4*)w)[t];
    float4 bv = ((const float4*)b)[t];
    float rx = (v.x - mu) * rstd * wv.x + bv.x;
    float ry = (v.y - mu) * rstd * wv.y + bv.y;
    float rz = (v.z - mu) * rstd * wv.z + bv.z;
    float rw = (v.w - mu) * rstd * wv.w + bv.w;
    yr[2 * t]     = __floats2half2_rn(rx, ry);
    yr[2 * t + 1] = __floats2half2_rn(rz, rw);
}

// ---------------------------------------------------------------------------
// LayerNorm (half input): one block (192 threads) per token; half output
// ---------------------------------------------------------------------------
__global__ void ln_h_kernel(const __half* __restrict__ x,
                            const float* __restrict__ w,
                            const float* __restrict__ b,
                            __half* __restrict__ y) {
    int tok = blockIdx.x;
    int t = threadIdx.x;
    const __half2* xr = (const __half2*)(x + (size_t)tok * Cc);
    __half2* yr = (__half2*)(y + (size_t)tok * Cc);

    float2 a = __half22float2(xr[2 * t]);
    float2 c = __half22float2(xr[2 * t + 1]);
    float s  = a.x + a.y + c.x + c.y;
    float ss = a.x*a.x + a.y*a.y + c.x*c.x + c.y*c.y;

    __shared__ float reds[6], redss[6];
    #pragma unroll
    for (int o = 16; o; o >>= 1) {
        s  += __shfl_xor_sync(0xffffffffu, s,  o);
        ss += __shfl_xor_sync(0xffffffffu, ss, o);
    }
    int wid = t >> 5, lid = t & 31;
    if (lid == 0) { reds[wid] = s; redss[wid] = ss; }
    __syncthreads();
    if (t < 32) {
        s  = (lid < 6) ? reds[lid]  : 0.f;
        ss = (lid < 6) ? redss[lid] : 0.f;
        #pragma unroll
        for (int o = 4; o; o >>= 1) {
            s  += __shfl_xor_sync(0xffffffffu, s,  o);
            ss += __shfl_xor_sync(0xffffffffu, ss, o);
        }
        if (lid == 0) { reds[0] = s; redss[0] = ss; }
    }
    __syncthreads();
    float mu  = reds[0] * (1.0f / Cc);
    float var = redss[0] * (1.0f / Cc) - mu * mu;
    float rstd = rsqrtf(var + 1e-5f);

    float4 wv = ((const float4*)w)[t];
    float4 bv = ((const float4*)b)[t];
    float rx = (a.x - mu) * rstd * wv.x + bv.x;
    float ry = (a.y - mu) * rstd * wv.y + bv.y;
    float rz = (c.x - mu) * rstd * wv.z + bv.z;
    float rw = (c.y - mu) * rstd * wv.w + bv.w;
    yr[2 * t]     = __floats2half2_rn(rx, ry);
    yr[2 * t + 1] = __floats2half2_rn(rz, rw);
}

// ---------------------------------------------------------------------------
// FP16 wmma GEMM (fp32 accumulate), 4-stage cp.async, 1 barrier/iter.
// Block 128x128, 8 warps (2m x 4n), warp tile 64x32. BK=32 halfs.
// ---------------------------------------------------------------------------
#define BM 128
#define BN 128
#define BKH 32
#define SSTRH 40
#define LDC 132
#define STAGES 4
#define NTHR 256
#define STAGE_H ((BM + BN) * SSTRH)            // 10240 halfs = 20480 B
#define PIPE_BYTES (STAGES * STAGE_H * 2)      // 81920
#define EPI_BYTES (BM * LDC * 4)               // 67584
#define GEMM_SMEM_BYTES (EPI_BYTES > PIPE_BYTES ? EPI_BYTES : PIPE_BYTES)

__device__ __forceinline__ void cp_async16(void* smem_dst, const void* gmem_src) {
    unsigned s = (unsigned)__cvta_generic_to_shared(smem_dst);
    asm volatile("cp.async.cg.shared.global [%0], [%1], 16;\n" :: "r"(s), "l"(gmem_src));
}
#define CP_COMMIT() asm volatile("cp.async.commit_group;\n" ::: "memory")
#define CP_WAIT_N(n) asm volatile("cp.async.wait_group %0;\n" :: "n"(n) : "memory")

template <bool RES, bool OUTH>
__global__ void __launch_bounds__(NTHR, 2) gemm_fp16(
        const __half* __restrict__ A,
        const __half* __restrict__ Wt,
        const float* __restrict__ bias,
        const float* __restrict__ res,
        float* __restrict__ Cout,
        __half* __restrict__ CoutH,
        int N, int K) {
    extern __shared__ __align__(16) char smem_raw[];
    __half* hs = (__half*)smem_raw;

    int tid = threadIdx.x;
    int m0 = blockIdx.y * BM;
    int n0 = blockIdx.x * BN;

    // load mapping: 2 threads per row, 2 x 16B chunks each
    int lrow = tid >> 1;
    int lc0  = (tid & 1) * 2;

    const __half* Abase = A  + (size_t)(m0 + lrow) * K + lc0 * 8;
    const __half* Bbase = Wt + (size_t)(n0 + lrow) * K + lc0 * 8;

    int wid = tid >> 5;
    int wm = (wid & 1) * 64;             // 2 warps m
    int wn = (wid >> 1) * 32;            // 4 warps n

    wmma::fragment<wmma::accumulator, 16, 16, 16, float> acc[4][2];
    #pragma unroll
    for (int i = 0; i < 4; i++)
        #pragma unroll
        for (int j = 0; j < 2; j++)
            wmma::fill_fragment(acc[i][j], 0.0f);

    const int nit = K / BKH;             // 24

    #pragma unroll
    for (int s = 0; s < STAGES - 1; s++) {
        __half* a = hs + s * STAGE_H + lrow * SSTRH + lc0 * 8;
        __half* b = hs + s * STAGE_H + BM * SSTRH + lrow * SSTRH + lc0 * 8;
        const __half* ag = Abase + s * BKH;
        const __half* bg = Bbase + s * BKH;
        #pragma unroll
        for (int c = 0; c < 2; c++) {
            cp_async16(a + c * 8, ag + c * 8);
            cp_async16(b + c * 8, bg + c * 8);
        }
        CP_COMMIT();
    }

    int sc_ = 0, sl_ = STAGES - 1;
    for (int it = 0; it < nit; it++) {
        CP_WAIT_N(STAGES - 2);
        __syncthreads();

        if (it + STAGES - 1 < nit) {
            __half* a = hs + sl_ * STAGE_H + lrow * SSTRH + lc0 * 8;
            __half* b = hs + sl_ * STAGE_H + BM * SSTRH + lrow * SSTRH + lc0 * 8;
            const __half* ag = Abase + (it + STAGES - 1) * BKH;
            const __half* bg = Bbase + (it + STAGES - 1) * BKH;
            #pragma unroll
            for (int c = 0; c < 2; c++) {
                cp_async16(a + c * 8, ag + c * 8);
                cp_async16(b + c * 8, bg + c * 8);
            }
        }
        CP_COMMIT();

        __half* Ac = hs + sc_ * STAGE_H;
        __half* Bc = Ac + BM * SSTRH;
        #pragma unroll
        for (int kk = 0; kk < BKH; kk += 16) {
            wmma::fragment<wmma::matrix_a, 16, 16, 16, __half, wmma::row_major> af[4];
            wmma::fragment<wmma::matrix_b, 16, 16, 16, __half, wmma::col_major> bf[2];
            #pragma unroll
            for (int i = 0; i < 4; i++)
                wmma::load_matrix_sync(af[i], &Ac[(wm + i * 16) * SSTRH + kk], SSTRH);
            #pragma unroll
            for (int j = 0; j < 2; j++)
                wmma::load_matrix_sync(bf[j], &Bc[(wn + j * 16) * SSTRH + kk], SSTRH);
            #pragma unroll
            for (int i = 0; i < 4; i++)
                #pragma unroll
                for (int j = 0; j < 2; j++)
                    wmma::mma_sync(acc[i][j], af[i], bf[j], acc[i][j]);
        }

        sc_ = (sc_ + 1 == STAGES) ? 0 : sc_ + 1;
        sl_ = (sl_ + 1 == STAGES) ? 0 : sl_ + 1;
    }
    CP_WAIT_N(0);
    __syncthreads();

    // Epilogue through shared (fp32)
    float* Cs = (float*)smem_raw;
    #pragma unroll
    for (int i = 0; i < 4; i++)
        #pragma unroll
        for (int j = 0; j < 2; j++)
            wmma::store_matrix_sync(&Cs[(wm + i * 16) * LDC + wn + j * 16],
                                    acc[i][j], LDC, wmma::mem_row_major);
    __syncthreads();

    if (OUTH) {
        #pragma unroll
        for (int i = 0; i < 32; i++) {
            int idx = tid + i * NTHR;
            int r = idx >> 6, c2 = idx & 63;
            float2 cs = *(const float2*)&Cs[r * LDC + c2 * 2];
            float2 bv = *(const float2*)(bias + n0 + c2 * 2);
            __half2 hv = __floats2half2_rn(cs.x + bv.x, cs.y + bv.y);
            *((__half2*)(CoutH + (size_t)(m0 + r) * N + n0) + c2) = hv;
        }
    } else {
        #pragma unroll
        for (int i = 0; i < 16; i++) {
            int idx = tid + i * NTHR;
            int r = idx >> 5, c4 = idx & 31;
            const float* cs = &Cs[r * LDC + c4 * 4];
            float4 bv = *(const float4*)(bias + n0 + c4 * 4);
            float4 v;
            v.x = cs[0] + bv.x; v.y = cs[1] + bv.y;
            v.z = cs[2] + bv.z; v.w = cs[3] + bv.w;
            size_t g = (size_t)(m0 + r) * N + n0 + c4 * 4;
            if (RES) {
                float4 rv = *(const float4*)(res + g);
                v.x += rv.x; v.y += rv.y; v.z += rv.z; v.w += rv.w;
            }
            *(float4*)(Cout + g) = v;
        }
    }
}

// ---------------------------------------------------------------------------
// Attention over time axis: one warp per (b,h,w,head) unit. T=16, HD=64.
// Half input (qkv), half output (o). Softmax/accum in fp32.
// ---------------------------------------------------------------------------
__global__ void attn_kernel(const __half* __restrict__ qkv,
                            __half* __restrict__ o) {
    int warp_in_blk = threadIdx.x >> 5;
    int lane = threadIdx.x & 31;
    int unit = blockIdx.x * 2 + warp_in_blk;   // 2 warps per block

    __shared__ __half2 sh2[2][3 * 16 * 36];    // q,k,v per warp
    __shared__ float sp[2][16 * 17];           // probs per warp
    __half2* q = sh2[warp_in_blk];
    __half2* k = q + 16 * 36;
    __half2* v = k + 16 * 36;
    float* p = sp[warp_in_blk];

    int head = unit % NHh;
    int s = unit / NHh;
    int w = s & 31; s >>= 5;
    int h = s & 31;
    int b = s >> 5;

    int spatial = h * 32 + w;

    // Load q,k,v (16 rows x 32 half2 each)
    for (int i = lane; i < 16 * 32; i += 32) {
        int t = i >> 5, d2 = i & 31;
        size_t g = ((size_t)((b * 16 + t) * 1024 + spatial)) * F3 + head * 192;
        const __half2* p2 = (const __half2*)(qkv + g);
        q[t * 36 + d2] = p2[d2];
        k[t * 36 + d2] = p2[32 + d2];
        v[t * 36 + d2] = p2[64 + d2];
    }
    __syncwarp();

    // Scores: lane pair per tq; each lane 8 tk
    int tq = lane >> 1;
    int tk0 = (lane & 1) * 8;
    float sc[8];
    #pragma unroll
    for (int j = 0; j < 8; j++) {
        float acc = 0.f;
        #pragma unroll
        for (int d2 = 0; d2 < 32; d2++) {
            float2 qf = __half22float2(q[tq * 36 + d2]);
            float2 kf = __half22float2(k[(tk0 + j) * 36 + d2]);
            acc += qf.x * kf.x + qf.y * kf.y;
        }
        sc[j] = acc * 0.125f;
    }
    float m = sc[0];
    #pragma unroll
    for (int j = 1; j < 8; j++) m = fmaxf(m, sc[j]);
    m = fmaxf(m, __shfl_xor_sync(0xffffffffu, m, 1));
    float sum = 0.f;
    #pragma unroll
    for (int j = 0; j < 8; j++) { sc[j] = __expf(sc[j] - m); sum += sc[j]; }
    sum += __shfl_xor_sync(0xffffffffu, sum, 1);
    float inv = 1.0f / sum;
    #pragma unroll
    for (int j = 0; j < 8; j++) p[tq * 17 + tk0 + j] = sc[j] * inv;
    __syncwarp();

    // o[t, d2=lane]: loop t; accumulate over tk in fp32; write half2
    for (int t = 0; t < 16; t++) {
        float2 acc = make_float2(0.f, 0.f);
        #pragma unroll
        for (int tk = 0; tk < 16; tk++) {
            float pw = p[t * 17 + tk];
            float2 vf = __half22float2(v[tk * 36 + lane]);
            acc.x += pw * vf.x;
            acc.y += pw * vf.y;
        }
        size_t g = ((size_t)((b * 16 + t) * 1024 + spatial)) * Cc + head * 64;
        *((__half2*)(o + g) + lane) = __floats2half2_rn(acc.x, acc.y);
    }
}

// ---------------------------------------------------------------------------
// Launch
// ---------------------------------------------------------------------------
extern "C" void kernel_launch(void* const* d_in, const int* in_sizes, int n_in,
                              void* d_out, int out_size) {
    const float* x     = (const float*)d_in[0];
    const float* ln1_w = (const float*)d_in[1];
    const float* ln1_b = (const float*)d_in[2];
    const float* Wqkv  = (const float*)d_in[3];
    const float* bqkv  = (const float*)d_in[4];
    const float* ln2_w = (const float*)d_in[5];
    const float* ln2_b = (const float*)d_in[6];
    const float* Wout  = (const float*)d_in[7];
    const float* bout  = (const float*)d_in[8];
    float* out = (float*)d_out;

    static __half *p_yh = nullptr, *p_qkvh = nullptr, *p_oh = nullptr,
                  *p_wqh = nullptr, *p_woh = nullptr;
    if (!p_yh) {
        cudaGetSymbolAddress((void**)&p_yh, g_yh);
        cudaGetSymbolAddress((void**)&p_qkvh, g_qkvh);
        cudaGetSymbolAddress((void**)&p_oh, g_oh);
        cudaGetSymbolAddress((void**)&p_wqh, g_wqh);
        cudaGetSymbolAddress((void**)&p_woh, g_woh);
        cudaFuncSetAttribute((const void*)gemm_fp16<false, true>,
                             cudaFuncAttributeMaxDynamicSharedMemorySize, GEMM_SMEM_BYTES);
        cudaFuncSetAttribute((const void*)gemm_fp16<true, false>,
                             cudaFuncAttributeMaxDynamicSharedMemorySize, GEMM_SMEM_BYTES);
    }

    // 0) weights -> half
    {
        int n4q = (F3 * Cc) / 4, n4o = (Cc * Cc) / 4;
        f2h_kernel<<<(n4q + 255) / 256, 256>>>(Wqkv, p_wqh, n4q);
        f2h_kernel<<<(n4o + 255) / 256, 256>>>(Wout, p_woh, n4o);
    }

    // 1) LN1 -> half
    ln_kernel<<<NTOK, 192>>>(x, ln1_w, ln1_b, p_yh);

    // 2) QKV GEMM (half output): (32768 x 2304)
    {
        dim3 grid(F3 / BN, NTOK / BM);     // 18 x 256
        gemm_fp16<false, true><<<grid, NTHR, GEMM_SMEM_BYTES>>>(
            p_yh, p_wqh, bqkv, nullptr, nullptr, p_qkvh, F3, Cc);
    }

    // 3) Attention (half in/out)
    {
        int nunits = Bb * Hh * Ww * NHh;   // 24576
        attn_kernel<<<nunits / 2, 64>>>(p_qkvh, p_oh);
    }

    // 4) LN2 (half in) -> half y
    ln_h_kernel<<<NTOK, 192>>>(p_oh, ln2_w, ln2_b, p_yh);

    // 5) Out GEMM + bias + residual: (32768 x 768), float output
    {
        dim3 grid(Cc / BN, NTOK / BM);     // 6 x 256
        gemm_fp16<true, false><<<grid, NTHR, GEMM_SMEM_BYTES>>>(
            p_yh, p_woh, bout, x, out, nullptr, Cc, Cc);
    }
}